// round 5
// baseline (speedup 1.0000x reference)
#include <cuda_runtime.h>
#include <stdint.h>

// kNN: B=2, N=2048, D=16, K=16. Output (B,N,K,2), written as FLOAT32:
// [...,0]=(float)batch, [...,1]=(float)neighbor_idx.
// (Reference computes int32 indices, but harness output dtype is float32 —
//  int-bit stores read back as denormals ~0, which exactly reproduces the
//  rel_err == 1.000000e+00 seen in rounds 1-4.)
//
// Kernel 1: transpose points AoS (B,N,16) -> __device__ SoA float4 scratch.
// Kernel 2: warp-per-query. Lanes scan candidates j = t*32+lane ascending,
// keep sorted top-16 (sqrt-dist bits + idx) in registers with stable strict-<
// insertion (ties -> lower index, matching jax.lax.top_k). Cross-lane merge:
// 16 rounds of warp-min over unique 64-bit keys (dist_bits<<32 | idx).

#define NPTS 2048
#define KNN  16
#define WPC  8
#define THREADS (WPC * 32)

__device__ float4 T4g[2][4][NPTS];   // 256 KB static scratch (allowed)

__global__ void transpose_kernel(const float* __restrict__ points)
{
    int idx = blockIdx.x * blockDim.x + threadIdx.x;   // b*8192 + c*2048 + j
    if (idx >= 2 * 4 * NPTS) return;
    int j = idx & (NPTS - 1);
    int c = (idx >> 11) & 3;
    int b = idx >> 13;
    const float4* P4 = reinterpret_cast<const float4*>(points);
    T4g[b][c][j] = P4[(b * NPTS + j) * 4 + c];
}

__global__ void knn_kernel(float2* __restrict__ out)
{
    const int b    = blockIdx.y;
    const int wid  = threadIdx.x >> 5;
    const int lane = threadIdx.x & 31;
    const int q    = blockIdx.x * WPC + wid;           // 0..2047 exactly

    const float4 q0 = T4g[b][0][q];
    const float4 q1 = T4g[b][1][q];
    const float4 q2 = T4g[b][2][q];
    const float4 q3 = T4g[b][3][q];

    unsigned D[16];
    int      J[16];
#pragma unroll
    for (int i = 0; i < 16; ++i) { D[i] = 0xFFFFFFFFu; J[i] = 0x7FFFFFFF; }

#pragma unroll 2
    for (int t = 0; t < NPTS / 32; ++t) {
        const int j = t * 32 + lane;

        float4 a0 = T4g[b][0][j];
        float4 a1 = T4g[b][1][j];
        float4 a2 = T4g[b][2][j];
        float4 a3 = T4g[b][3][j];

        // Sequential c=0..15 accumulation (matches reference reduce order).
        float s = 0.0f, d;
        d = q0.x - a0.x; s = fmaf(d, d, s);
        d = q0.y - a0.y; s = fmaf(d, d, s);
        d = q0.z - a0.z; s = fmaf(d, d, s);
        d = q0.w - a0.w; s = fmaf(d, d, s);
        d = q1.x - a1.x; s = fmaf(d, d, s);
        d = q1.y - a1.y; s = fmaf(d, d, s);
        d = q1.z - a1.z; s = fmaf(d, d, s);
        d = q1.w - a1.w; s = fmaf(d, d, s);
        d = q2.x - a2.x; s = fmaf(d, d, s);
        d = q2.y - a2.y; s = fmaf(d, d, s);
        d = q2.z - a2.z; s = fmaf(d, d, s);
        d = q2.w - a2.w; s = fmaf(d, d, s);
        d = q3.x - a3.x; s = fmaf(d, d, s);
        d = q3.y - a3.y; s = fmaf(d, d, s);
        d = q3.z - a3.z; s = fmaf(d, d, s);
        d = q3.w - a3.w; s = fmaf(d, d, s);

        const float dist = __fsqrt_rn(s);              // compare post-sqrt
        unsigned kb = __float_as_uint(dist);
        if (j == q) kb = 0xFFFFFFFFu;                  // exclude self

        if (kb < D[15]) {                              // stable strict-<
            D[15] = kb; J[15] = j;
#pragma unroll
            for (int i = 15; i > 0; --i) {
                if (D[i] < D[i - 1]) {
                    unsigned td = D[i]; D[i] = D[i - 1]; D[i - 1] = td;
                    int      tj = J[i]; J[i] = J[i - 1]; J[i - 1] = tj;
                }
            }
        }
    }

    // 16 rounds of warp-min over unique 64-bit keys; winner lane pops.
    float2* outp = out + ((size_t)b * NPTS + q) * KNN;
    const float fb = (float)b;
    unsigned long long h = ((unsigned long long)D[0] << 32) | (unsigned)J[0];
#pragma unroll
    for (int r = 0; r < KNN; ++r) {
        unsigned long long v = h;
#pragma unroll
        for (int off = 16; off > 0; off >>= 1) {
            unsigned long long o = __shfl_xor_sync(0xFFFFFFFFu, v, off);
            v = (o < v) ? o : v;
        }
        if (lane == 0)
            outp[r] = make_float2(fb, (float)(int)(unsigned)(v & 0xFFFFFFFFull));
        if (h == v) {
#pragma unroll
            for (int i = 0; i < 15; ++i) { D[i] = D[i + 1]; J[i] = J[i + 1]; }
            D[15] = 0xFFFFFFFFu; J[15] = 0x7FFFFFFF;
            h = ((unsigned long long)D[0] << 32) | (unsigned)J[0];
        }
    }
}

extern "C" void kernel_launch(void* const* d_in, const int* in_sizes, int n_in,
                              void* d_out, int out_size)
{
    // points (2*2048*16) is the SMALLER input (features is 4x larger);
    // comparison valid whether in_sizes is elements or bytes.
    const float* points;
    if (n_in >= 2) {
        points = (in_sizes[0] <= in_sizes[1]) ? (const float*)d_in[0]
                                              : (const float*)d_in[1];
    } else {
        points = (const float*)d_in[0];
    }

    transpose_kernel<<<(2 * 4 * NPTS + 255) / 256, 256>>>(points);

    dim3 grid(NPTS / WPC, 2);
    knn_kernel<<<grid, THREADS>>>((float2*)d_out);
}

// round 6
// speedup vs baseline: 1.5068x; 1.5068x over previous
#include <cuda_runtime.h>
#include <stdint.h>

// kNN: B=2, N=2048, D=16, K=16. Output (B,N,K,2) as FLOAT32: [b, idx].
//
// transpose_kernel: AoS points -> SoA float4 scratch (coalesced loads).
// knn_kernel: warp-per-query; per-lane sorted top-8 (stable strict-<, ties ->
// lower index = jax.lax.top_k), 16-round warp-min merge over 64-bit keys
// (dist_bits<<32 | idx). Exactness guard: if any lane's full 8 entries get
// popped, rerun that query with per-lane depth 16 (SMEM scratch, rare).

#define NPTS 2048
#define KNN  16
#define KL   8                 // per-lane kept (fast path)
#define WPC  8
#define THREADS (WPC * 32)

__device__ float4 T4g[2][4][NPTS];   // 256 KB static scratch

__global__ void transpose_kernel(const float* __restrict__ points)
{
    int idx = blockIdx.x * blockDim.x + threadIdx.x;   // b*8192 + c*2048 + j
    if (idx >= 2 * 4 * NPTS) return;
    int j = idx & (NPTS - 1);
    int c = (idx >> 11) & 3;
    int b = idx >> 13;
    const float4* P4 = reinterpret_cast<const float4*>(points);
    T4g[b][c][j] = P4[(b * NPTS + j) * 4 + c];
}

__device__ __forceinline__ unsigned dist_key(
    float4 q0, float4 q1, float4 q2, float4 q3,
    float4 a0, float4 a1, float4 a2, float4 a3)
{
    float s = 0.0f, d;
    d = q0.x - a0.x; s = fmaf(d, d, s);
    d = q0.y - a0.y; s = fmaf(d, d, s);
    d = q0.z - a0.z; s = fmaf(d, d, s);
    d = q0.w - a0.w; s = fmaf(d, d, s);
    d = q1.x - a1.x; s = fmaf(d, d, s);
    d = q1.y - a1.y; s = fmaf(d, d, s);
    d = q1.z - a1.z; s = fmaf(d, d, s);
    d = q1.w - a1.w; s = fmaf(d, d, s);
    d = q2.x - a2.x; s = fmaf(d, d, s);
    d = q2.y - a2.y; s = fmaf(d, d, s);
    d = q2.z - a2.z; s = fmaf(d, d, s);
    d = q2.w - a2.w; s = fmaf(d, d, s);
    d = q3.x - a3.x; s = fmaf(d, d, s);
    d = q3.y - a3.y; s = fmaf(d, d, s);
    d = q3.z - a3.z; s = fmaf(d, d, s);
    d = q3.w - a3.w; s = fmaf(d, d, s);
    return __float_as_uint(__fsqrt_rn(s));   // compare post-sqrt (ref semantics)
}

__global__ void knn_kernel(float2* __restrict__ out)
{
    // Thread-private scratch for the (rare) exact-depth-16 fallback.
    __shared__ unsigned sD[WPC][KNN][32];
    __shared__ int      sJ[WPC][KNN][32];

    const int b    = blockIdx.y;
    const int wid  = threadIdx.x >> 5;
    const int lane = threadIdx.x & 31;
    const int q    = blockIdx.x * WPC + wid;           // 0..2047 exactly

    const float4 q0 = T4g[b][0][q];
    const float4 q1 = T4g[b][1][q];
    const float4 q2 = T4g[b][2][q];
    const float4 q3 = T4g[b][3][q];

    // Fast path: per-lane sorted top-8.
    unsigned D[KL];
    int      J[KL];
#pragma unroll
    for (int i = 0; i < KL; ++i) { D[i] = 0xFFFFFFFFu; J[i] = 0x7FFFFFFF; }

#pragma unroll 2
    for (int t = 0; t < NPTS / 32; ++t) {
        const int j = t * 32 + lane;
        float4 a0 = T4g[b][0][j];
        float4 a1 = T4g[b][1][j];
        float4 a2 = T4g[b][2][j];
        float4 a3 = T4g[b][3][j];
        unsigned kb = dist_key(q0, q1, q2, q3, a0, a1, a2, a3);
        if (j == q) kb = 0xFFFFFFFFu;                  // exclude self

        if (kb < D[KL - 1]) {                          // stable strict-<
            D[KL - 1] = kb; J[KL - 1] = j;
#pragma unroll
            for (int i = KL - 1; i > 0; --i) {
                if (D[i] < D[i - 1]) {
                    unsigned td = D[i]; D[i] = D[i - 1]; D[i - 1] = td;
                    int      tj = J[i]; J[i] = J[i - 1]; J[i - 1] = tj;
                }
            }
        }
    }

    // Merge: 16 rounds of warp-min over unique 64-bit keys; count pops/lane.
    float2* outp = out + ((size_t)b * NPTS + q) * KNN;
    const float fb = (float)b;
    int cnt = 0;
    unsigned long long h = ((unsigned long long)D[0] << 32) | (unsigned)J[0];
#pragma unroll
    for (int r = 0; r < KNN; ++r) {
        unsigned long long v = h;
#pragma unroll
        for (int off = 16; off > 0; off >>= 1) {
            unsigned long long o = __shfl_xor_sync(0xFFFFFFFFu, v, off);
            v = (o < v) ? o : v;
        }
        if (lane == 0)
            outp[r] = make_float2(fb, (float)(int)(unsigned)(v & 0xFFFFFFFFull));
        if (h == v) {                                  // unique keys: one winner
            ++cnt;
#pragma unroll
            for (int i = 0; i < KL - 1; ++i) { D[i] = D[i + 1]; J[i] = J[i + 1]; }
            D[KL - 1] = 0xFFFFFFFFu; J[KL - 1] = 0x7FFFFFFF;
            h = ((unsigned long long)D[0] << 32) | (unsigned)J[0];
        }
    }

    // Exactness guard: a lane whose full 8 got popped may have discarded a
    // true top-16 member. Rerun this query at depth 16 (P ~ 1e-3 per run).
    if (__ballot_sync(0xFFFFFFFFu, cnt == KL) != 0) {
#pragma unroll 1
        for (int i = 0; i < KNN; ++i) { sD[wid][i][lane] = 0xFFFFFFFFu; sJ[wid][i][lane] = 0x7FFFFFFF; }
#pragma unroll 1
        for (int t = 0; t < NPTS / 32; ++t) {
            const int j = t * 32 + lane;
            float4 a0 = T4g[b][0][j];
            float4 a1 = T4g[b][1][j];
            float4 a2 = T4g[b][2][j];
            float4 a3 = T4g[b][3][j];
            unsigned kb = dist_key(q0, q1, q2, q3, a0, a1, a2, a3);
            if (j == q) continue;
            if (kb < sD[wid][KNN - 1][lane]) {
                int p = KNN - 1;
#pragma unroll 1
                while (p > 0 && kb < sD[wid][p - 1][lane]) {
                    sD[wid][p][lane] = sD[wid][p - 1][lane];
                    sJ[wid][p][lane] = sJ[wid][p - 1][lane];
                    --p;
                }
                sD[wid][p][lane] = kb; sJ[wid][p][lane] = j;
            }
        }
        int cur = 0;
        unsigned long long h2 = ((unsigned long long)sD[wid][0][lane] << 32)
                              | (unsigned)sJ[wid][0][lane];
#pragma unroll 1
        for (int r = 0; r < KNN; ++r) {
            unsigned long long v = h2;
#pragma unroll
            for (int off = 16; off > 0; off >>= 1) {
                unsigned long long o = __shfl_xor_sync(0xFFFFFFFFu, v, off);
                v = (o < v) ? o : v;
            }
            if (lane == 0)
                outp[r] = make_float2(fb, (float)(int)(unsigned)(v & 0xFFFFFFFFull));
            if (h2 == v) {
                ++cur;
                h2 = (cur < KNN)
                   ? (((unsigned long long)sD[wid][cur][lane] << 32) | (unsigned)sJ[wid][cur][lane])
                   : 0xFFFFFFFFFFFFFFFFull;
            }
        }
    }
}

extern "C" void kernel_launch(void* const* d_in, const int* in_sizes, int n_in,
                              void* d_out, int out_size)
{
    // points (2*2048*16) is the SMALLER input (features is 4x larger).
    const float* points;
    if (n_in >= 2) {
        points = (in_sizes[0] <= in_sizes[1]) ? (const float*)d_in[0]
                                              : (const float*)d_in[1];
    } else {
        points = (const float*)d_in[0];
    }

    transpose_kernel<<<(2 * 4 * NPTS + 255) / 256, 256>>>(points);

    dim3 grid(NPTS / WPC, 2);
    knn_kernel<<<grid, THREADS>>>((float2*)d_out);
}